// round 8
// baseline (speedup 1.0000x reference)
#include <cuda_runtime.h>

#define N_NODES 100000
#define N_EDGES 1600000
#define DIM 128
#define HID 16
#define NCLS 40
#define BN_EPS 1e-5f

#define NBLK 296
#define NTHR 256
#define GSZ  (NBLK * NTHR)
#define NWARPS (NBLK * (NTHR / 32))
#define N_PAIRS (N_NODES / 2)
#define STATS_TILE 64
#define N_TILES ((N_NODES + STATS_TILE - 1) / STATS_TILE)

typedef unsigned long long ull;

// ---------------- f32x2 packed-math helpers (B300 FFMA2 path) --------------
__device__ __forceinline__ ull pack2(float x, float y) {
    ull r; asm("mov.b64 %0,{%1,%2};" : "=l"(r) : "f"(x), "f"(y)); return r;
}
__device__ __forceinline__ void unpack2(ull v, float& x, float& y) {
    asm("mov.b64 {%0,%1},%2;" : "=f"(x), "=f"(y) : "l"(v));
}
__device__ __forceinline__ ull fma2(ull a, ull b, ull c) {
    ull d; asm("fma.rn.f32x2 %0,%1,%2,%3;" : "=l"(d) : "l"(a), "l"(b), "l"(c)); return d;
}
__device__ __forceinline__ ull add2(ull a, ull b) {
    ull d; asm("add.rn.f32x2 %0,%1,%2;" : "=l"(d) : "l"(a), "l"(b)); return d;
}

// ---------------- globals --------------------------------------------------
__device__ float  g_h1[N_NODES * HID];
__device__ float  g_s1[N_NODES * HID];
__device__ float  g_agg[N_NODES * HID];
__device__ double g_M3[3][HID * HID];
__device__ double g_sum3[3][HID];
__device__ int    g_row_ptr[N_NODES + 1];
__device__ unsigned int g_bar = 0;
__device__ volatile unsigned int g_epoch = 0;

// ---------------- shared memory union (per phase) ---------------------------
struct SmemGemm {
    float W2s[HID * DIM];
    float W1s[DIM * HID];
    float scl[DIM];
    float sft[DIM];
    float Mc[HID * HID];
    double Ss[HID];
};
struct SmemStats { float rows[STATS_TILE * HID]; };
struct SmemOut   { float Ws[HID * NCLS]; float bs[NCLS]; };

// ---------------- global barrier (sense via monotonic epoch) ---------------
__device__ __forceinline__ void gbar(unsigned int& epoch) {
    __syncthreads();
    if (threadIdx.x == 0) {
        epoch++;
        __threadfence();
        unsigned int old = atomicAdd(&g_bar, 1u);
        if (old == NBLK - 1) {
            g_bar = 0;
            __threadfence();
            g_epoch = epoch;
        } else {
            while (g_epoch < epoch) __nanosleep(64);
            __threadfence();
        }
    }
    __syncthreads();
}

// ---------------- spmm phase: warp per row pair, strided --------------------
template<bool RELU>
__device__ void spmm_phase(const float* __restrict__ h, const float* __restrict__ vals,
                           const int* __restrict__ col, const float* __restrict__ bias,
                           float* __restrict__ out, int gwarp) {
    const ull* h8 = reinterpret_cast<const ull*>(h);
    int lane = threadIdx.x & 31;
    int q = lane & 7;
    int sub = lane >> 3;
    float b0 = 0.f, b1 = 0.f;
    if (RELU) { b0 = bias[2 * q]; b1 = bias[2 * q + 1]; }
    for (int p = gwarp; p < N_PAIRS; p += NWARPS) {
        int r0 = p * 2;
        int a0 = g_row_ptr[r0];
        int a1 = g_row_ptr[r0 + 1];
        int a2 = g_row_ptr[r0 + 2];
        int len = a2 - a0;
        ull accA = 0ull, accB = 0ull;
        for (int off = sub * 8; off < len; off += 32) {
            #pragma unroll
            for (int i = 0; i < 8; i++) {
                int o = off + i;
                bool valid = (o < len);
                int idx = valid ? (a0 + o) : (a2 - 1);
                float v = vals[idx];
                if (!valid) v = 0.f;
                int c = col[idx];
                ull hv = h8[(size_t)c * 8 + q];
                float vA = ((a0 + o) < a1) ? v : 0.f;
                float vB = v - vA;
                accA = fma2(pack2(vA, vA), hv, accA);
                accB = fma2(pack2(vB, vB), hv, accB);
            }
        }
        accA = add2(accA, __shfl_xor_sync(0xffffffffu, accA, 8));
        accA = add2(accA, __shfl_xor_sync(0xffffffffu, accA, 16));
        accB = add2(accB, __shfl_xor_sync(0xffffffffu, accB, 8));
        accB = add2(accB, __shfl_xor_sync(0xffffffffu, accB, 16));
        if (sub == 0) {
            float x0, x1, y0, y1;
            unpack2(accA, x0, x1);
            unpack2(accB, y0, y1);
            if (RELU) {
                x0 = fmaxf(x0 + b0, 0.f); x1 = fmaxf(x1 + b1, 0.f);
                y0 = fmaxf(y0 + b0, 0.f); y1 = fmaxf(y1 + b1, 0.f);
            }
            float2* o2 = reinterpret_cast<float2*>(out);
            o2[(size_t)r0 * 8 + q]       = make_float2(x0, x1);
            o2[(size_t)(r0 + 1) * 8 + q] = make_float2(y0, y1);
        }
    }
}

// ============================================================================
__global__ void __launch_bounds__(NTHR, 2)
mega_kernel(const float* __restrict__ x, const float* __restrict__ vals,
            const float* __restrict__ W1, const float* __restrict__ b1,
            const float* __restrict__ W2, const float* __restrict__ gamma,
            const float* __restrict__ beta, const float* __restrict__ W1f,
            const float* __restrict__ b1f, const float* __restrict__ W2f,
            const float* __restrict__ b2f, const int* __restrict__ row,
            const int* __restrict__ col, float* __restrict__ out) {
    __shared__ union { SmemGemm g; SmemStats s; SmemOut o; } sm;
    int t = threadIdx.x;
    int gtid = blockIdx.x * NTHR + t;
    int gwarp = gtid >> 5;
    unsigned int epoch = 0;
    if (t == 0) g_epoch = 0;   // safe: all resets precede all barrier-1 arrivals

    // ================= phase 0: row_ptr + zero stats + h1 = x @ W1[0] =======
    for (int i = gtid; i <= N_NODES; i += GSZ) {
        int lo = 0, hi = N_EDGES;
        while (lo < hi) {
            int mid = (lo + hi) >> 1;
            if (row[mid] < i) lo = mid + 1; else hi = mid;
        }
        g_row_ptr[i] = lo;
    }
    if (blockIdx.x == 0) {
        if (t < HID * HID) { g_M3[0][t] = 0.0; g_M3[1][t] = 0.0; g_M3[2][t] = 0.0; }
        if (t < HID) { g_sum3[0][t] = 0.0; g_sum3[1][t] = 0.0; g_sum3[2][t] = 0.0; }
    }
    for (int i = t; i < DIM * HID; i += NTHR) sm.g.W1s[i] = W1[i];
    __syncthreads();
    for (int n = gtid; n < N_NODES; n += GSZ) {
        ull acc2[8];
        #pragma unroll
        for (int j = 0; j < 8; j++) acc2[j] = 0ull;
        const float4* xr = reinterpret_cast<const float4*>(x + (size_t)n * DIM);
        #pragma unroll 4
        for (int d4 = 0; d4 < DIM / 4; d4++) {
            float4 xv = xr[d4];
            #pragma unroll
            for (int dd = 0; dd < 4; dd++) {
                float xd = (&xv.x)[dd];
                ull xb = pack2(xd, xd);
                const ulonglong2* wr =
                    reinterpret_cast<const ulonglong2*>(&sm.g.W1s[(d4 * 4 + dd) * HID]);
                #pragma unroll
                for (int p = 0; p < 4; p++) {
                    ulonglong2 w = wr[p];
                    acc2[p * 2 + 0] = fma2(xb, w.x, acc2[p * 2 + 0]);
                    acc2[p * 2 + 1] = fma2(xb, w.y, acc2[p * 2 + 1]);
                }
            }
        }
        ull* yr = reinterpret_cast<ull*>(g_h1 + (size_t)n * HID);
        #pragma unroll
        for (int j = 0; j < 8; j++) yr[j] = acc2[j];
    }
    gbar(epoch);

    // ================= 3 GCN+BN layers =======================================
    for (int L = 0; L < 3; L++) {
        // --- A: s1 = relu(spmm(h1) + b1[L])
        spmm_phase<true>(g_h1, vals, col, b1 + L * HID, g_s1, gwarp);
        gbar(epoch);
        // --- B: agg = spmm(s1)
        spmm_phase<false>(g_s1, vals, col, nullptr, g_agg, gwarp);
        gbar(epoch);
        // --- C: stats partials -> g_M3[L], g_sum3[L]
        {
            int j = t >> 4, k = t & 15;
            float m0 = 0.f, m1 = 0.f, m2 = 0.f, m3 = 0.f;
            float s0 = 0.f, s1v = 0.f, s2 = 0.f, s3 = 0.f;
            for (int tile = blockIdx.x; tile < N_TILES; tile += NBLK) {
                int r0 = tile * STATS_TILE;
                int nr = min(STATS_TILE, N_NODES - r0);
                __syncthreads();
                if (t < nr * 4)
                    reinterpret_cast<float4*>(sm.s.rows)[t] =
                        reinterpret_cast<const float4*>(g_agg + (size_t)r0 * HID)[t];
                __syncthreads();
                #pragma unroll 2
                for (int rr = 0; rr + 4 <= nr; rr += 4) {
                    float aj0 = sm.s.rows[(rr + 0) * HID + j], ak0 = sm.s.rows[(rr + 0) * HID + k];
                    float aj1 = sm.s.rows[(rr + 1) * HID + j], ak1 = sm.s.rows[(rr + 1) * HID + k];
                    float aj2 = sm.s.rows[(rr + 2) * HID + j], ak2 = sm.s.rows[(rr + 2) * HID + k];
                    float aj3 = sm.s.rows[(rr + 3) * HID + j], ak3 = sm.s.rows[(rr + 3) * HID + k];
                    m0 += aj0 * ak0; m1 += aj1 * ak1; m2 += aj2 * ak2; m3 += aj3 * ak3;
                    if (j == 0) { s0 += ak0; s1v += ak1; s2 += ak2; s3 += ak3; }
                }
            }
            atomicAdd(&g_M3[L][t], (double)((m0 + m1) + (m2 + m3)));
            if (j == 0) atomicAdd(&g_sum3[L][k], (double)((s0 + s1v) + (s2 + s3)));
        }
        gbar(epoch);
        // --- D: every block computes BN affine, then fused bn+gemm ----------
        {
            int j = t >> 4, k = t & 15;
            if (t < HID) sm.g.Ss[t] = g_sum3[L][t];
            __syncthreads();
            const double invN = 1.0 / (double)N_NODES;
            sm.g.Mc[t] = (float)(g_M3[L][t] - sm.g.Ss[j] * sm.g.Ss[k] * invN);
            __syncthreads();
            const float* W2L = W2 + (size_t)L * HID * DIM;
            if (t < DIM) {
                float wf[HID];
                #pragma unroll
                for (int kk = 0; kk < HID; kk++) wf[kk] = W2L[kk * DIM + t];
                double sn = 0.0;
                #pragma unroll
                for (int kk = 0; kk < HID; kk++) sn += sm.g.Ss[kk] * (double)wf[kk];
                sn *= invN;
                float q0 = 0.f, q1 = 0.f, q2 = 0.f, q3 = 0.f;
                #pragma unroll
                for (int a = 0; a < HID; a++) {
                    float wa = wf[a];
                    #pragma unroll
                    for (int b = 0; b < HID; b += 4) {
                        q0 += sm.g.Mc[a * HID + b + 0] * (wa * wf[b + 0]);
                        q1 += sm.g.Mc[a * HID + b + 1] * (wa * wf[b + 1]);
                        q2 += sm.g.Mc[a * HID + b + 2] * (wa * wf[b + 2]);
                        q3 += sm.g.Mc[a * HID + b + 3] * (wa * wf[b + 3]);
                    }
                }
                float var = ((q0 + q1) + (q2 + q3)) * (float)invN;
                float scale = rsqrtf(fmaxf(var, 0.f) + BN_EPS) * gamma[L * DIM + t];
                sm.g.scl[t] = scale;
                sm.g.sft[t] = beta[L * DIM + t] - (float)sn * scale;
            }
            const float* W1n = (L < 2) ? (W1 + (size_t)(L + 1) * DIM * HID) : W1f;
            for (int i = t; i < HID * DIM; i += NTHR) {
                sm.g.W2s[i] = W2L[i];
                sm.g.W1s[i] = W1n[i];
            }
            __syncthreads();
            for (int n = gtid; n < N_NODES; n += GSZ) {
                ull a2[HID];
                const float4* ar = reinterpret_cast<const float4*>(g_agg + (size_t)n * HID);
                #pragma unroll
                for (int k4 = 0; k4 < 4; k4++) {
                    float4 v = ar[k4];
                    a2[k4*4+0] = pack2(v.x, v.x);
                    a2[k4*4+1] = pack2(v.y, v.y);
                    a2[k4*4+2] = pack2(v.z, v.z);
                    a2[k4*4+3] = pack2(v.w, v.w);
                }
                ull acc2[8];
                #pragma unroll
                for (int jj = 0; jj < 8; jj++) acc2[jj] = 0ull;
                #pragma unroll 2
                for (int cb = 0; cb < DIM; cb += 4) {
                    ull t01 = 0ull, t23 = 0ull;
                    const ulonglong2* w2p = reinterpret_cast<const ulonglong2*>(&sm.g.W2s[cb]);
                    #pragma unroll
                    for (int kk = 0; kk < HID; kk++) {
                        ulonglong2 w = w2p[kk * (DIM / 4)];
                        t01 = fma2(a2[kk], w.x, t01);
                        t23 = fma2(a2[kk], w.y, t23);
                    }
                    ulonglong2 sc = *reinterpret_cast<const ulonglong2*>(&sm.g.scl[cb]);
                    ulonglong2 sf = *reinterpret_cast<const ulonglong2*>(&sm.g.sft[cb]);
                    t01 = fma2(t01, sc.x, sf.x);
                    t23 = fma2(t23, sc.y, sf.y);
                    float v0, v1, v2, v3;
                    unpack2(t01, v0, v1);
                    unpack2(t23, v2, v3);
                    v0 = fmaxf(v0, 0.f); v1 = fmaxf(v1, 0.f);
                    v2 = fmaxf(v2, 0.f); v3 = fmaxf(v3, 0.f);
                    ull vb[4] = { pack2(v0, v0), pack2(v1, v1), pack2(v2, v2), pack2(v3, v3) };
                    #pragma unroll
                    for (int c = 0; c < 4; c++) {
                        const ulonglong2* w1p =
                            reinterpret_cast<const ulonglong2*>(&sm.g.W1s[(cb + c) * HID]);
                        #pragma unroll
                        for (int p = 0; p < 4; p++) {
                            ulonglong2 w = w1p[p];
                            acc2[p * 2 + 0] = fma2(vb[c], w.x, acc2[p * 2 + 0]);
                            acc2[p * 2 + 1] = fma2(vb[c], w.y, acc2[p * 2 + 1]);
                        }
                    }
                }
                ull* yr = reinterpret_cast<ull*>(g_h1 + (size_t)n * HID);
                #pragma unroll
                for (int jj = 0; jj < 8; jj++) yr[jj] = acc2[jj];
            }
        }
        gbar(epoch);
    }

    // ================= final head ============================================
    spmm_phase<true>(g_h1, vals, col, b1f, g_s1, gwarp);
    gbar(epoch);
    spmm_phase<false>(g_s1, vals, col, nullptr, g_agg, gwarp);
    gbar(epoch);
    // out = agg @ W2f + b2f
    for (int i = t; i < HID * NCLS; i += NTHR) sm.o.Ws[i] = W2f[i];
    if (t < NCLS) sm.o.bs[t] = b2f[t];
    __syncthreads();
    for (int n = gtid; n < N_NODES; n += GSZ) {
        ull a2[HID];
        const float4* ar = reinterpret_cast<const float4*>(g_agg + (size_t)n * HID);
        #pragma unroll
        for (int k4 = 0; k4 < 4; k4++) {
            float4 v = ar[k4];
            a2[k4*4+0] = pack2(v.x, v.x);
            a2[k4*4+1] = pack2(v.y, v.y);
            a2[k4*4+2] = pack2(v.z, v.z);
            a2[k4*4+3] = pack2(v.w, v.w);
        }
        ull o2[NCLS / 2];
        const ull* bp = reinterpret_cast<const ull*>(sm.o.bs);
        #pragma unroll
        for (int p = 0; p < NCLS / 2; p++) o2[p] = bp[p];
        #pragma unroll
        for (int k = 0; k < HID; k++) {
            const ull* wr = reinterpret_cast<const ull*>(&sm.o.Ws[k * NCLS]);
            #pragma unroll
            for (int p = 0; p < NCLS / 2; p++)
                o2[p] = fma2(a2[k], wr[p], o2[p]);
        }
        ull* orow = reinterpret_cast<ull*>(out + (size_t)n * NCLS);
        #pragma unroll
        for (int p = 0; p < NCLS / 2; p++) orow[p] = o2[p];
    }
}

// ============================================================================
extern "C" void kernel_launch(void* const* d_in, const int* in_sizes, int n_in,
                              void* d_out, int out_size) {
    const float* x     = (const float*)d_in[0];
    const float* vals  = (const float*)d_in[1];
    const float* W1    = (const float*)d_in[2];   // (3,128,16)
    const float* b1    = (const float*)d_in[3];   // (3,16)
    const float* W2    = (const float*)d_in[4];   // (3,16,128)
    const float* gamma = (const float*)d_in[6];   // (3,128)
    const float* beta  = (const float*)d_in[7];   // (3,128)
    const float* W1f   = (const float*)d_in[8];   // (128,16)
    const float* b1f   = (const float*)d_in[9];   // (16,)
    const float* W2f   = (const float*)d_in[10];  // (16,40)
    const float* b2f   = (const float*)d_in[11];  // (40,)
    const int*   row   = (const int*)d_in[12];
    const int*   col   = (const int*)d_in[13];
    float* out = (float*)d_out;
    // d_in[5] (b2) cancels inside batchnorm.

    mega_kernel<<<NBLK, NTHR>>>(x, vals, W1, b1, W2, gamma, beta,
                                W1f, b1f, W2f, b2f, row, col, out);
}

// round 9
// speedup vs baseline: 1.4076x; 1.4076x over previous
#include <cuda_runtime.h>

#define N_NODES 100000
#define N_EDGES 1600000
#define DIM 128
#define HID 16
#define NCLS 40
#define BN_EPS 1e-5f

typedef unsigned long long ull;

// ---------------- f32x2 packed-math helpers (B300 FFMA2 path) --------------
__device__ __forceinline__ ull pack2(float x, float y) {
    ull r; asm("mov.b64 %0,{%1,%2};" : "=l"(r) : "f"(x), "f"(y)); return r;
}
__device__ __forceinline__ void unpack2(ull v, float& x, float& y) {
    asm("mov.b64 {%0,%1},%2;" : "=f"(x), "=f"(y) : "l"(v));
}
__device__ __forceinline__ ull fma2(ull a, ull b, ull c) {
    ull d; asm("fma.rn.f32x2 %0,%1,%2,%3;" : "=l"(d) : "l"(a), "l"(b), "l"(c)); return d;
}
__device__ __forceinline__ ull add2(ull a, ull b) {
    ull d; asm("add.rn.f32x2 %0,%1,%2;" : "=l"(d) : "l"(a), "l"(b)); return d;
}

// ---------------- scratch (static device globals) ---------------------------
__device__ float  g_h1[N_NODES * HID];
__device__ float  g_s1[N_NODES * HID];
__device__ float  g_agg[N_NODES * HID];
__device__ double g_sum16[HID];
__device__ double g_M[HID * HID];
__device__ float  g_scale[DIM];
__device__ float  g_shift[DIM];
__device__ int    g_row_ptr[N_NODES + 1];
__device__ unsigned int g_cnt = 0;

#define TB 256
#define NODE_BLK ((N_NODES + TB - 1) / TB)          // 391
#define RP_BLK   ((N_NODES + 1 + TB - 1) / TB)      // 391
#define N_PAIRS  (N_NODES / 2)                      // 50000
#define SPMM_BLK (N_PAIRS / 8)                      // 6250 (8 warps/block, warp=pair)
#define STATS_G  592
#define STATS_TILE 64
#define N_TILES  ((N_NODES + STATS_TILE - 1) / STATS_TILE)   // 1563

// ---------------- fused: row_ptr build + stats zero + x@W1 ------------------
__global__ void prolog_kernel(const int* __restrict__ row, const float* __restrict__ x,
                              const float* __restrict__ W, float* __restrict__ y) {
    if (blockIdx.x >= NODE_BLK) {
        int t = threadIdx.x;
        if (blockIdx.x == NODE_BLK) {
            if (t < HID * HID) g_M[t] = 0.0;
            if (t < HID) g_sum16[t] = 0.0;
            if (t == 0) g_cnt = 0;
        }
        int i = (blockIdx.x - NODE_BLK) * TB + t;
        if (i > N_NODES) return;
        int lo = 0, hi = N_EDGES;
        while (lo < hi) {
            int mid = (lo + hi) >> 1;
            if (row[mid] < i) lo = mid + 1; else hi = mid;
        }
        g_row_ptr[i] = lo;
        return;
    }
    __shared__ __align__(16) float Ws[DIM * HID];
    for (int i = threadIdx.x; i < DIM * HID; i += TB) Ws[i] = W[i];
    __syncthreads();
    int n = blockIdx.x * TB + threadIdx.x;
    if (n >= N_NODES) return;
    ull acc2[8];
    #pragma unroll
    for (int j = 0; j < 8; j++) acc2[j] = 0ull;
    const float4* xr = reinterpret_cast<const float4*>(x + (size_t)n * DIM);
    #pragma unroll 4
    for (int d4 = 0; d4 < DIM / 4; d4++) {
        float4 xv = xr[d4];
        #pragma unroll
        for (int dd = 0; dd < 4; dd++) {
            float xd = (&xv.x)[dd];
            ull xb = pack2(xd, xd);
            const ulonglong2* wr = reinterpret_cast<const ulonglong2*>(&Ws[(d4 * 4 + dd) * HID]);
            #pragma unroll
            for (int p = 0; p < 4; p++) {
                ulonglong2 w = wr[p];
                acc2[p * 2 + 0] = fma2(xb, w.x, acc2[p * 2 + 0]);
                acc2[p * 2 + 1] = fma2(xb, w.y, acc2[p * 2 + 1]);
            }
        }
    }
    ull* yr = reinterpret_cast<ull*>(y + (size_t)n * HID);
    #pragma unroll
    for (int j = 0; j < 8; j++) yr[j] = acc2[j];
}

// ---------------- 16-wide SpMM v4: warp per row pair, staged edges ----------
// Lanes = (sub 0..7) x (q 0..3). Staging: lane e loads col/vals of edge base+e
// (coalesced, 1 LDG each per 32 edges). Inner: 4 steps; per step each thread
// gathers 16B (LDG.128) of edge sub*4+i, with c/v broadcast via shfl.idx.
// Row routing (pair) via vA/vB select into two f32x2x2 accumulators.
template<bool RELU>
__global__ void spmm16(const float* __restrict__ h, const float* __restrict__ vals,
                       const int* __restrict__ col, const float* __restrict__ bias,
                       float* __restrict__ out) {
    int t = threadIdx.x;
    int lane = t & 31;
    int warp = t >> 5;
    int q = lane & 3;            // 16B piece 0..3
    int sub = lane >> 2;         // 0..7
    int r0 = (blockIdx.x * 8 + warp) * 2;
    int a0 = g_row_ptr[r0];
    int a1 = g_row_ptr[r0 + 1];
    int a2 = g_row_ptr[r0 + 2];
    int len = a2 - a0;
    const ulonglong2* h16 = reinterpret_cast<const ulonglong2*>(h);
    ull accA0 = 0ull, accA1 = 0ull, accB0 = 0ull, accB1 = 0ull;
    for (int base = 0; base < len; base += 32) {
        // ---- stage 32 edges (lane = edge) ----
        int o = base + lane;
        int oc = min(o, len - 1);
        int idx = a0 + oc;
        int c = col[idx];
        float v = (o < len) ? vals[idx] : 0.f;
        float vA = ((a0 + o) < a1) ? v : 0.f;   // o>=len => v=0 => both 0
        float vB = v - vA;
        // ---- 4 steps x 8 edges ----
        #pragma unroll
        for (int i = 0; i < 4; i++) {
            int src = sub * 4 + i;
            int   cc = __shfl_sync(0xffffffffu, c,  src);
            float va = __shfl_sync(0xffffffffu, vA, src);
            float vb = __shfl_sync(0xffffffffu, vB, src);
            ulonglong2 hv = h16[(size_t)cc * 4 + q];
            ull va2 = pack2(va, va);
            ull vb2 = pack2(vb, vb);
            accA0 = fma2(va2, hv.x, accA0);
            accA1 = fma2(va2, hv.y, accA1);
            accB0 = fma2(vb2, hv.x, accB0);
            accB1 = fma2(vb2, hv.y, accB1);
        }
    }
    // reduce across 8 subs (lanes differing in bits 2..4)
    #pragma unroll
    for (int m = 4; m <= 16; m <<= 1) {
        accA0 = add2(accA0, __shfl_xor_sync(0xffffffffu, accA0, m));
        accA1 = add2(accA1, __shfl_xor_sync(0xffffffffu, accA1, m));
        accB0 = add2(accB0, __shfl_xor_sync(0xffffffffu, accB0, m));
        accB1 = add2(accB1, __shfl_xor_sync(0xffffffffu, accB1, m));
    }
    if (sub == 0) {
        float a0f, a1f, a2f, a3f, b0f, b1f, b2f, b3f;
        unpack2(accA0, a0f, a1f); unpack2(accA1, a2f, a3f);
        unpack2(accB0, b0f, b1f); unpack2(accB1, b2f, b3f);
        if (RELU) {
            float4 bb = reinterpret_cast<const float4*>(bias)[q];
            a0f = fmaxf(a0f + bb.x, 0.f); a1f = fmaxf(a1f + bb.y, 0.f);
            a2f = fmaxf(a2f + bb.z, 0.f); a3f = fmaxf(a3f + bb.w, 0.f);
            b0f = fmaxf(b0f + bb.x, 0.f); b1f = fmaxf(b1f + bb.y, 0.f);
            b2f = fmaxf(b2f + bb.z, 0.f); b3f = fmaxf(b3f + bb.w, 0.f);
        }
        float4* o4 = reinterpret_cast<float4*>(out);
        o4[(size_t)r0 * 4 + q]       = make_float4(a0f, a1f, a2f, a3f);
        o4[(size_t)(r0 + 1) * 4 + q] = make_float4(b0f, b1f, b2f, b3f);
    }
}

// ---------------- stats + BN prep: centered covariance, fp32 epilogue -------
__global__ void __launch_bounds__(TB, 6)
stats16_bn(const float* __restrict__ agg, const float* __restrict__ W2,
           const float* __restrict__ gamma, const float* __restrict__ beta) {
    __shared__ __align__(16) float rows[STATS_TILE * HID];   // 4KB
    int t = threadIdx.x;
    int j = t >> 4, k = t & 15;
    float m0 = 0.f, m1 = 0.f, m2 = 0.f, m3 = 0.f;
    float s0 = 0.f, s1 = 0.f, s2 = 0.f, s3 = 0.f;
    for (int tile = blockIdx.x; tile < N_TILES; tile += STATS_G) {
        int r0 = tile * STATS_TILE;
        int nr = min(STATS_TILE, N_NODES - r0);
        __syncthreads();
        if (t < nr * 4)
            reinterpret_cast<float4*>(rows)[t] =
                reinterpret_cast<const float4*>(agg + (size_t)r0 * HID)[t];
        __syncthreads();
        #pragma unroll 2
        for (int rr = 0; rr + 4 <= nr; rr += 4) {
            float aj0 = rows[(rr + 0) * HID + j], ak0 = rows[(rr + 0) * HID + k];
            float aj1 = rows[(rr + 1) * HID + j], ak1 = rows[(rr + 1) * HID + k];
            float aj2 = rows[(rr + 2) * HID + j], ak2 = rows[(rr + 2) * HID + k];
            float aj3 = rows[(rr + 3) * HID + j], ak3 = rows[(rr + 3) * HID + k];
            m0 += aj0 * ak0; m1 += aj1 * ak1; m2 += aj2 * ak2; m3 += aj3 * ak3;
            if (j == 0) { s0 += ak0; s1 += ak1; s2 += ak2; s3 += ak3; }
        }
    }
    atomicAdd(&g_M[t], (double)((m0 + m1) + (m2 + m3)));
    if (j == 0) atomicAdd(&g_sum16[k], (double)((s0 + s1) + (s2 + s3)));

    __threadfence();
    __shared__ unsigned int sIsLast;
    if (t == 0) {
        unsigned int old = atomicAdd(&g_cnt, 1u);
        sIsLast = (old == gridDim.x - 1) ? 1u : 0u;
    }
    __syncthreads();
    if (!sIsLast) return;
    __shared__ float  Mc[HID * HID];
    __shared__ double Ss[HID];
    if (t < HID) Ss[t] = g_sum16[t];
    __syncthreads();
    const double invN = 1.0 / (double)N_NODES;
    Mc[t] = (float)(g_M[t] - Ss[j] * Ss[k] * invN);
    __syncthreads();
    if (t < DIM) {
        float wf[HID];
        #pragma unroll
        for (int kk = 0; kk < HID; kk++) wf[kk] = W2[kk * DIM + t];
        double sn = 0.0;
        #pragma unroll
        for (int kk = 0; kk < HID; kk++) sn += Ss[kk] * (double)wf[kk];
        sn *= invN;
        float q0 = 0.f, q1 = 0.f, q2 = 0.f, q3 = 0.f;
        #pragma unroll
        for (int a = 0; a < HID; a++) {
            float wa = wf[a];
            #pragma unroll
            for (int b = 0; b < HID; b += 4) {
                q0 += Mc[a * HID + b + 0] * (wa * wf[b + 0]);
                q1 += Mc[a * HID + b + 1] * (wa * wf[b + 1]);
                q2 += Mc[a * HID + b + 2] * (wa * wf[b + 2]);
                q3 += Mc[a * HID + b + 3] * (wa * wf[b + 3]);
            }
        }
        float var = ((q0 + q1) + (q2 + q3)) * (float)invN;
        float scale = rsqrtf(fmaxf(var, 0.f) + BN_EPS) * gamma[t];
        g_scale[t] = scale;
        g_shift[t] = beta[t] - (float)sn * scale;   // b2 cancels in (h2-mean)
    }
    __syncthreads();
    g_M[t] = 0.0;
    if (t < HID) g_sum16[t] = 0.0;
    if (t == 0) g_cnt = 0;
}

// ---------------- fused: h1 = relu(bn(agg@W2)) @ W1next  (f32x2 packed) -----
__global__ void fused_bn_gemm(const float* __restrict__ agg, const float* __restrict__ W2,
                              const float* __restrict__ W1n, float* __restrict__ y) {
    __shared__ __align__(16) float W2s[HID * DIM];
    __shared__ __align__(16) float W1s[DIM * HID];
    __shared__ __align__(16) float scl[DIM];
    __shared__ __align__(16) float sft[DIM];
    for (int i = threadIdx.x; i < HID * DIM; i += TB) {
        W2s[i] = W2[i];
        W1s[i] = W1n[i];
    }
    for (int i = threadIdx.x; i < DIM; i += TB) {
        scl[i] = g_scale[i];
        sft[i] = g_shift[i];
    }
    __syncthreads();
    int n = blockIdx.x * TB + threadIdx.x;
    if (n >= N_NODES) return;
    ull a2[HID];
    {
        const float4* ar = reinterpret_cast<const float4*>(agg + (size_t)n * HID);
        #pragma unroll
        for (int k4 = 0; k4 < 4; k4++) {
            float4 v = ar[k4];
            a2[k4*4+0] = pack2(v.x, v.x);
            a2[k4*4+1] = pack2(v.y, v.y);
            a2[k4*4+2] = pack2(v.z, v.z);
            a2[k4*4+3] = pack2(v.w, v.w);
        }
    }
    ull acc2[8];
    #pragma unroll
    for (int j = 0; j < 8; j++) acc2[j] = 0ull;
    #pragma unroll 2
    for (int cb = 0; cb < DIM; cb += 4) {
        ull t01 = 0ull, t23 = 0ull;
        const ulonglong2* w2p = reinterpret_cast<const ulonglong2*>(&W2s[cb]);
        #pragma unroll
        for (int k = 0; k < HID; k++) {
            ulonglong2 w = w2p[k * (DIM / 4)];
            t01 = fma2(a2[k], w.x, t01);
            t23 = fma2(a2[k], w.y, t23);
        }
        ulonglong2 sc = *reinterpret_cast<const ulonglong2*>(&scl[cb]);
        ulonglong2 sf = *reinterpret_cast<const ulonglong2*>(&sft[cb]);
        t01 = fma2(t01, sc.x, sf.x);
        t23 = fma2(t23, sc.y, sf.y);
        float v0, v1, v2, v3;
        unpack2(t01, v0, v1);
        unpack2(t23, v2, v3);
        v0 = fmaxf(v0, 0.f); v1 = fmaxf(v1, 0.f);
        v2 = fmaxf(v2, 0.f); v3 = fmaxf(v3, 0.f);
        ull vb[4] = { pack2(v0, v0), pack2(v1, v1), pack2(v2, v2), pack2(v3, v3) };
        #pragma unroll
        for (int c = 0; c < 4; c++) {
            const ulonglong2* w1p = reinterpret_cast<const ulonglong2*>(&W1s[(cb + c) * HID]);
            #pragma unroll
            for (int p = 0; p < 4; p++) {
                ulonglong2 w = w1p[p];
                acc2[p * 2 + 0] = fma2(vb[c], w.x, acc2[p * 2 + 0]);
                acc2[p * 2 + 1] = fma2(vb[c], w.y, acc2[p * 2 + 1]);
            }
        }
    }
    ull* yr = reinterpret_cast<ull*>(y + (size_t)n * HID);
    #pragma unroll
    for (int j = 0; j < 8; j++) yr[j] = acc2[j];
}

// ---------------- out[N,40] = agg[N,16] @ W[16,40] + b  (f32x2 packed) ------
__global__ void out_gemm(const float* __restrict__ agg, const float* __restrict__ W,
                         const float* __restrict__ b, float* __restrict__ out) {
    __shared__ __align__(16) float Ws[HID * NCLS];
    __shared__ __align__(16) float bs[NCLS];
    for (int i = threadIdx.x; i < HID * NCLS; i += TB) Ws[i] = W[i];
    if (threadIdx.x < NCLS) bs[threadIdx.x] = b[threadIdx.x];
    __syncthreads();
    int n = blockIdx.x * TB + threadIdx.x;
    if (n >= N_NODES) return;
    ull a2[HID];
    {
        const float4* ar = reinterpret_cast<const float4*>(agg + (size_t)n * HID);
        #pragma unroll
        for (int k4 = 0; k4 < 4; k4++) {
            float4 v = ar[k4];
            a2[k4*4+0] = pack2(v.x, v.x);
            a2[k4*4+1] = pack2(v.y, v.y);
            a2[k4*4+2] = pack2(v.z, v.z);
            a2[k4*4+3] = pack2(v.w, v.w);
        }
    }
    ull o2[NCLS / 2];
    const ull* bp = reinterpret_cast<const ull*>(bs);
    #pragma unroll
    for (int p = 0; p < NCLS / 2; p++) o2[p] = bp[p];
    #pragma unroll
    for (int k = 0; k < HID; k++) {
        const ull* wr = reinterpret_cast<const ull*>(&Ws[k * NCLS]);
        #pragma unroll
        for (int p = 0; p < NCLS / 2; p++)
            o2[p] = fma2(a2[k], wr[p], o2[p]);
    }
    ull* orow = reinterpret_cast<ull*>(out + (size_t)n * NCLS);
    #pragma unroll
    for (int p = 0; p < NCLS / 2; p++) orow[p] = o2[p];
}

// ============================================================================
extern "C" void kernel_launch(void* const* d_in, const int* in_sizes, int n_in,
                              void* d_out, int out_size) {
    const float* x     = (const float*)d_in[0];
    const float* vals  = (const float*)d_in[1];
    const float* W1    = (const float*)d_in[2];   // (3,128,16)
    const float* b1    = (const float*)d_in[3];   // (3,16)
    const float* W2    = (const float*)d_in[4];   // (3,16,128)
    const float* gamma = (const float*)d_in[6];   // (3,128)
    const float* beta  = (const float*)d_in[7];   // (3,128)
    const float* W1f   = (const float*)d_in[8];   // (128,16)
    const float* b1f   = (const float*)d_in[9];   // (16,)
    const float* W2f   = (const float*)d_in[10];  // (16,40)
    const float* b2f   = (const float*)d_in[11];  // (40,)
    const int*   row   = (const int*)d_in[12];
    const int*   col   = (const int*)d_in[13];
    float* out = (float*)d_out;
    // d_in[5] (b2) cancels inside batchnorm.

    float *p_h1, *p_s1, *p_agg;
    cudaGetSymbolAddress((void**)&p_h1,  g_h1);
    cudaGetSymbolAddress((void**)&p_s1,  g_s1);
    cudaGetSymbolAddress((void**)&p_agg, g_agg);

    prolog_kernel<<<NODE_BLK + RP_BLK, TB>>>(row, x, W1, p_h1);

    for (int i = 0; i < 3; i++) {
        spmm16<true><<<SPMM_BLK, TB>>>(p_h1, vals, col, b1 + i * HID, p_s1);
        spmm16<false><<<SPMM_BLK, TB>>>(p_s1, vals, col, nullptr, p_agg);
        stats16_bn<<<STATS_G, TB>>>(p_agg, W2 + (size_t)i * HID * DIM,
                                    gamma + i * DIM, beta + i * DIM);
        const float* Wnext = (i < 2) ? (W1 + (size_t)(i + 1) * DIM * HID) : W1f;
        fused_bn_gemm<<<NODE_BLK, TB>>>(p_agg, W2 + (size_t)i * HID * DIM, Wnext, p_h1);
    }

    spmm16<true><<<SPMM_BLK, TB>>>(p_h1, vals, col, b1f, p_s1);
    spmm16<false><<<SPMM_BLK, TB>>>(p_s1, vals, col, nullptr, p_agg);
    out_gemm<<<NODE_BLK, TB>>>(p_agg, W2f, b2f, out);
}